// round 17
// baseline (speedup 1.0000x reference)
#include <cuda_runtime.h>
#include <cuda_bf16.h>
#include <cstdint>

// R12 structure (global folded table + PDL overlap + branchless loop) with:
//  - st.global.cs.v8.f32 (streaming hint restored at 256-bit width)
//  - float4-vectorized build_table (shorter PDL producer)
//
// Folded table (i-independent):
//   rows   0..4  : C[c] = W[65] + W[131] + W[133+c]   (diff chain, HOT: ~98.4%)
//   row    5     : W[132]                             (entity row)
//   rows   6..70 : A[r] = W[r] + W[131] + W[138]      (same chain, dres!=0)
//   rows  71..135: B[t] = W[32] + W[66+t] + W[138]    (same chain, dres==0)

#define TAB_ROWS 136

__device__ __align__(32) float g_table[TAB_ROWS * 128];

__global__ void build_table(const float* __restrict__ W)
{
    const int idx = blockIdx.x * blockDim.x + threadIdx.x;  // float4 granularity
    if (idx < TAB_ROWS * 32) {
        const int r = idx >> 5;
        const int e = idx & 31;
        const float4* __restrict__ W4 = (const float4*)W;
        float4 v;
        if (r < 5) {
            const float4 a = W4[65 * 32 + e], b = W4[131 * 32 + e], c = W4[(133 + r) * 32 + e];
            v.x = a.x + b.x + c.x; v.y = a.y + b.y + c.y;
            v.z = a.z + b.z + c.z; v.w = a.w + b.w + c.w;
        } else if (r == 5) {
            v = W4[132 * 32 + e];
        } else if (r < 71) {
            const float4 a = W4[(r - 6) * 32 + e], b = W4[131 * 32 + e], c = W4[138 * 32 + e];
            v.x = a.x + b.x + c.x; v.y = a.y + b.y + c.y;
            v.z = a.z + b.z + c.z; v.w = a.w + b.w + c.w;
        } else {
            const float4 a = W4[32 * 32 + e], b = W4[(66 + (r - 71)) * 32 + e], c = W4[138 * 32 + e];
            v.x = a.x + b.x + c.x; v.y = a.y + b.y + c.y;
            v.z = a.z + b.z + c.z; v.w = a.w + b.w + c.w;
        }
        ((float4*)g_table)[idx] = v;
    }
    cudaTriggerProgrammaticLaunchCompletion();
}

__device__ __forceinline__ void stg256_cs(float* p, const float4& a, const float4& b)
{
    asm volatile("st.global.cs.v8.f32 [%0], {%1,%2,%3,%4,%5,%6,%7,%8};"
                 :: "l"(p),
                    "f"(a.x), "f"(a.y), "f"(a.z), "f"(a.w),
                    "f"(b.x), "f"(b.y), "f"(b.z), "f"(b.w)
                 : "memory");
}

__global__ void __launch_bounds__(256, 7)
rpe_main(const float* __restrict__ feats, float* __restrict__ out, int n)
{
    __shared__ int jidx[1024];

    const int tid = threadIdx.x;
    const int i   = blockIdx.x;

    // ---- Phase A: per-j packed index (row | ent<<8) — no table access ----
    const float res_i  = feats[i * 10 + 0];
    const float tok_i  = feats[i * 10 + 1];
    const float asym_i = feats[i * 10 + 2];
    const float ent_i  = feats[i * 10 + 3];
    const float sym_i  = feats[i * 10 + 4];

    for (int j = tid; j < n; j += 256) {
        const float res_j  = feats[j * 10 + 0];
        const float tok_j  = feats[j * 10 + 1];
        const float asym_j = feats[j * 10 + 2];
        const float ent_j  = feats[j * 10 + 3];
        const float sym_j  = feats[j * 10 + 4];

        int row;
        if (asym_i == asym_j) {
            const int dres = (int)(res_i - res_j);
            if (dres != 0) {
                row = 6 + min(max(dres + 32, 0), 64);          // A table
            } else {
                const int dtok = (int)(tok_i - tok_j);
                row = 71 + min(max(dtok + 32, 0), 64);         // B table
            }
        } else {
            row = min(max((int)(sym_i - sym_j) + 2, 0), 4);    // C table (hot)
        }
        const int ent = (ent_i == ent_j) ? 1 : 0;
        jidx[j] = row | (ent << 8);
    }

    // wait for build_table's writes (PDL dependency point)
    cudaGridDependencySynchronize();
    __syncthreads();

    // ---- Phase B: warp = 2 rows, 16 lanes x 32B each, STG.256.cs ----
    const int lane = tid & 31;
    const int e8   = lane & 15;          // 32B column within the 512B row
    const int pair = lane >> 4;          // which of the 2 rows this half-warp owns
    const int wid  = tid >> 5;           // 8 warps -> 16 rows per sweep

    const float4* __restrict__ T4 = (const float4*)g_table;

    // entity row (32B) in registers
    const float4 went_lo = __ldg(&T4[5 * 32 + 2 * e8]);
    const float4 went_hi = __ldg(&T4[5 * 32 + 2 * e8 + 1]);

    float* __restrict__ out_i = out + ((size_t)i * (size_t)n) * 128;

    for (int j0 = wid * 2; j0 < n; j0 += 16) {
        const int j = j0 + pair;
        const int p = jidx[j];                       // LDS (2 values/warp, bcast)
        const int base = (p & 255) * 32 + 2 * e8;

        float4 lo = __ldg(&T4[base]);
        float4 hi = __ldg(&T4[base + 1]);
        if (p >> 8) {
            lo.x += went_lo.x; lo.y += went_lo.y; lo.z += went_lo.z; lo.w += went_lo.w;
            hi.x += went_hi.x; hi.y += went_hi.y; hi.z += went_hi.z; hi.w += went_hi.w;
        }
        stg256_cs(out_i + (size_t)j * 128 + e8 * 8, lo, hi);
    }
}

extern "C" void kernel_launch(void* const* d_in, const int* in_sizes, int n_in,
                              void* d_out, int out_size)
{
    const float* feats = (const float*)d_in[0];   // [1, n, 10] f32
    const float* W     = (const float*)d_in[1];   // [139, 128] f32
    float* out         = (float*)d_out;           // [1, n, n, 128] f32

    const int n = in_sizes[0] / 10;               // b == 1 (n == 1024)

    build_table<<<(TAB_ROWS * 32 + 255) / 256, 256>>>(W);

    // PDL launch: rpe_main may start while build_table is still running.
    cudaLaunchConfig_t cfg = {};
    cfg.gridDim  = dim3(n, 1, 1);
    cfg.blockDim = dim3(256, 1, 1);
    cudaLaunchAttribute attr[1];
    attr[0].id = cudaLaunchAttributeProgrammaticStreamSerialization;
    attr[0].val.programmaticStreamSerializationAllowed = 1;
    cfg.attrs    = attr;
    cfg.numAttrs = 1;
    cudaLaunchKernelEx(&cfg, rpe_main, feats, out, n);
}